// round 2
// baseline (speedup 1.0000x reference)
#include <cuda_runtime.h>

// RescaleProbMask: x (32,256,256,16) fp32
//   p[h][w] = mean over (b,c) of x[b,h,w,c]
//   out = (p>=ALPHA) ? x*ALPHA/p : 1 - beta*(1-x),  beta=(1-ALPHA)/(1-p)
// Both branches are affine in x: out = scale*x + offset.
//
// Fused single-pass: CTA = (h, 32-wide w tile). Stage 64 KiB in SMEM
// (32 b x 512 contiguous floats each, coalesced float4), reduce in SMEM,
// map + store. Total HBM traffic = 1 read + 1 write = 256 MiB.

#define ALPHA_C 0.25f

constexpr int B = 32, H = 256, W = 256, C = 16;
constexpr int WT = 32;                       // w per tile
constexpr int THREADS = 512;
constexpr int CHUNK_FLOATS = WT * C;         // 512 floats per b-slice
constexpr int CHUNK_F4 = CHUNK_FLOATS / 4;   // 128 float4 per b-slice
constexpr int TILE_F4 = B * CHUNK_F4;        // 4096 float4 = 64 KiB
constexpr int ROW_F4 = W * C / 4;            // 1024 float4 per (b,h) row
constexpr long long BATCH_F4 = (long long)H * W * C / 4;  // 262144

__global__ __launch_bounds__(THREADS, 2)
void rescale_prob_mask_kernel(const float4* __restrict__ x4,
                              float4* __restrict__ o4) {
    extern __shared__ float4 s4[];           // TILE_F4 float4 (64 KiB)
    __shared__ float s_scale[WT];
    __shared__ float s_off[WT];

    const int h  = blockIdx.y;               // 0..255
    const int wt = blockIdx.x;               // 0..7
    const int tid = threadIdx.x;

    const long long base = (long long)h * ROW_F4 + (long long)wt * CHUNK_F4;

    // ---- load tile: 4096 float4, 8 per thread, fully coalesced ----
    #pragma unroll
    for (int it = 0; it < TILE_F4 / THREADS; ++it) {
        int f = it * THREADS + tid;
        int b = f >> 7;                      // f / 128
        int within = f & 127;
        s4[f] = x4[(long long)b * BATCH_F4 + base + within];
    }
    __syncthreads();

    // ---- reduce: 16 threads per w, each sums its c over all b ----
    {
        const float* s = reinterpret_cast<const float*>(s4);
        int wloc = tid >> 4;                 // 0..31
        int c    = tid & 15;
        float acc = 0.f;
        #pragma unroll
        for (int b = 0; b < B; ++b)
            acc += s[b * CHUNK_FLOATS + wloc * C + c];
        // 16-lane butterfly (lane 0 / lane 16 of each half-warp end up clean)
        #pragma unroll
        for (int off = 8; off > 0; off >>= 1)
            acc += __shfl_down_sync(0xFFFFFFFFu, acc, off);
        if (c == 0) {
            float p = acc * (1.0f / (float)(B * C));
            float scale, offset;
            if (p >= ALPHA_C) {
                scale = ALPHA_C / p;
                offset = 0.0f;
            } else {
                float beta = (1.0f - ALPHA_C) / (1.0f - p);
                scale = beta;
                offset = 1.0f - beta;
            }
            s_scale[wloc] = scale;
            s_off[wloc]   = offset;
        }
    }
    __syncthreads();

    // ---- map + store: out = scale*x + offset ----
    #pragma unroll
    for (int it = 0; it < TILE_F4 / THREADS; ++it) {
        int f = it * THREADS + tid;
        int b = f >> 7;
        int within = f & 127;
        int wl = within >> 2;                // 4 float4 per w (16 floats)
        float sc = s_scale[wl];
        float of = s_off[wl];
        float4 v = s4[f];
        float4 r;
        r.x = fmaf(v.x, sc, of);
        r.y = fmaf(v.y, sc, of);
        r.z = fmaf(v.z, sc, of);
        r.w = fmaf(v.w, sc, of);
        o4[(long long)b * BATCH_F4 + base + within] = r;
    }
}

extern "C" void kernel_launch(void* const* d_in, const int* in_sizes, int n_in,
                              void* d_out, int out_size) {
    (void)in_sizes; (void)n_in; (void)out_size;
    const float4* x4 = (const float4*)d_in[0];
    float4* o4 = (float4*)d_out;

    const int smem = TILE_F4 * sizeof(float4);   // 64 KiB dynamic
    cudaFuncSetAttribute(rescale_prob_mask_kernel,
                         cudaFuncAttributeMaxDynamicSharedMemorySize, smem);

    dim3 grid(W / WT, H);                    // (8, 256) = 2048 CTAs
    rescale_prob_mask_kernel<<<grid, THREADS, smem>>>(x4, o4);
}